// round 2
// baseline (speedup 1.0000x reference)
#include <cuda_runtime.h>
#include <math.h>

#define NN 8192
#define KK 64

// ---------------- device scratch (no allocations allowed) ----------------
__device__ double g_within;
__device__ float  g_rowsum[NN];
__device__ float  g_colsum[NN];
__device__ int    g_ids[NN];
__device__ float  g_cnt[KK], g_sx[KK], g_sy[KK], g_ds[KK];
__device__ int    g_maxid;

// ---------------- zero accumulators (graph replays must reset) -----------
__global__ void k_zero() {
    int i = blockIdx.x * blockDim.x + threadIdx.x;
    if (i == 0) { g_within = 0.0; g_maxid = 0; }
    if (i < KK) { g_cnt[i] = 0.f; g_sx[i] = 0.f; g_sy[i] = 0.f; g_ds[i] = 0.f; }
    if (i < NN) { g_rowsum[i] = 0.f; g_colsum[i] = 0.f; }
}

// ---------------- within = sum_ik A_ik * (E@A)_ik -------------------------
// grid (64, 8): blockIdx.x -> 128-row tile of i, blockIdx.y -> 1024-wide j chunk
// block 256 threads (16x16), each computes an 8(i) x 4(k) fp32 micro-tile.
__global__ __launch_bounds__(256) void k_within(const float* __restrict__ E,
                                                const float* __restrict__ A) {
    __shared__ float Es[128][33];   // +1 pad -> conflict-free read & write
    __shared__ float As[32][64];

    const int i0 = blockIdx.x * 128;
    const int j0 = blockIdx.y * 1024;
    const int tx = threadIdx.x & 15;
    const int ty = threadIdx.x >> 4;

    float acc[8][4];
#pragma unroll
    for (int r = 0; r < 8; r++)
#pragma unroll
        for (int c = 0; c < 4; c++) acc[r][c] = 0.f;

    for (int jc = 0; jc < 1024; jc += 32) {
        const int jb = j0 + jc;
        // load E tile 128x32 (coalesced: 32 consecutive j per warp row)
        {
            const int c  = threadIdx.x & 31;
            const int r0 = threadIdx.x >> 5;
#pragma unroll
            for (int p = 0; p < 16; p++) {
                int r = r0 + p * 8;
                Es[r][c] = E[(size_t)(i0 + r) * NN + (jb + c)];
            }
        }
        // load A tile 32x64
#pragma unroll
        for (int p = 0; p < 8; p++) {
            int idx = threadIdx.x + p * 256;
            int r = idx >> 6, c = idx & 63;
            As[r][c] = A[(size_t)(jb + r) * KK + c];
        }
        __syncthreads();

#pragma unroll 8
        for (int jj = 0; jj < 32; jj++) {
            float4 av = *(const float4*)&As[jj][tx * 4];
            float e[8];
#pragma unroll
            for (int r = 0; r < 8; r++) e[r] = Es[ty * 8 + r][jj];
#pragma unroll
            for (int r = 0; r < 8; r++) {
                acc[r][0] = fmaf(e[r], av.x, acc[r][0]);
                acc[r][1] = fmaf(e[r], av.y, acc[r][1]);
                acc[r][2] = fmaf(e[r], av.z, acc[r][2]);
                acc[r][3] = fmaf(e[r], av.w, acc[r][3]);
            }
        }
        __syncthreads();
    }

    // epilogue: partial within = sum acc[r][c] * A[i, k]
    float part = 0.f;
#pragma unroll
    for (int r = 0; r < 8; r++) {
        float4 av = *(const float4*)&A[(size_t)(i0 + ty * 8 + r) * KK + tx * 4];
        part = fmaf(acc[r][0], av.x, part);
        part = fmaf(acc[r][1], av.y, part);
        part = fmaf(acc[r][2], av.z, part);
        part = fmaf(acc[r][3], av.w, part);
    }
#pragma unroll
    for (int o = 16; o > 0; o >>= 1) part += __shfl_xor_sync(0xffffffffu, part, o);

    __shared__ double warpsum[8];
    if ((threadIdx.x & 31) == 0) warpsum[threadIdx.x >> 5] = (double)part;
    __syncthreads();
    if (threadIdx.x == 0) {
        double s = 0.0;
#pragma unroll
        for (int w = 0; w < 8; w++) s += warpsum[w];
        atomicAdd(&g_within, s);
    }
}

// ---------------- rowsum / colsum of E ------------------------------------
// 256 blocks x 256 threads; block b owns rows [32b, 32b+32).
__global__ __launch_bounds__(256) void k_rowcol(const float* __restrict__ E) {
    const int rowbase = blockIdx.x * 32;
    const int t = threadIdx.x;
    float4 csum[8];
#pragma unroll
    for (int p = 0; p < 8; p++) csum[p] = make_float4(0.f, 0.f, 0.f, 0.f);

    for (int r = 0; r < 32; r++) {
        const float4* Erow = (const float4*)(E + (size_t)(rowbase + r) * NN);
        float rs = 0.f;
#pragma unroll
        for (int p = 0; p < 8; p++) {
            float4 v = Erow[t + p * 256];
            csum[p].x += v.x; csum[p].y += v.y; csum[p].z += v.z; csum[p].w += v.w;
            rs += (v.x + v.y) + (v.z + v.w);
        }
#pragma unroll
        for (int o = 16; o > 0; o >>= 1) rs += __shfl_xor_sync(0xffffffffu, rs, o);
        if ((t & 31) == 0) atomicAdd(&g_rowsum[rowbase + r], rs);
    }
#pragma unroll
    for (int p = 0; p < 8; p++) {
        int c = (t + p * 256) * 4;
        atomicAdd(&g_colsum[c + 0], csum[p].x);
        atomicAdd(&g_colsum[c + 1], csum[p].y);
        atomicAdd(&g_colsum[c + 2], csum[p].z);
        atomicAdd(&g_colsum[c + 3], csum[p].w);
    }
}

// ---------------- spatial loss: argmax + segment sums ---------------------
__global__ void k_spatial1(const float* __restrict__ A, const float* __restrict__ pos) {
    int i = blockIdx.x * blockDim.x + threadIdx.x;
    if (i >= NN) return;
    const float4* a4 = (const float4*)(A + (size_t)i * KK);
    float best = -3.402823466e+38f;
    int bi = 0;
#pragma unroll
    for (int q = 0; q < 16; q++) {
        float4 v = a4[q];
        if (v.x > best) { best = v.x; bi = q * 4 + 0; }
        if (v.y > best) { best = v.y; bi = q * 4 + 1; }
        if (v.z > best) { best = v.z; bi = q * 4 + 2; }
        if (v.w > best) { best = v.w; bi = q * 4 + 3; }
    }
    g_ids[i] = bi;
    atomicAdd(&g_cnt[bi], 1.0f);
    atomicAdd(&g_sx[bi], pos[2 * i]);
    atomicAdd(&g_sy[bi], pos[2 * i + 1]);
    atomicMax(&g_maxid, bi);
}

__global__ void k_spatial2(const float* __restrict__ pos) {
    int i = blockIdx.x * blockDim.x + threadIdx.x;
    if (i >= NN) return;
    int c = g_ids[i];
    float cnt = g_cnt[c] + 1e-6f;
    float cx = g_sx[c] / cnt, cy = g_sy[c] / cnt;
    float dx = pos[2 * i] - cx, dy = pos[2 * i + 1] - cy;
    atomicAdd(&g_ds[c], sqrtf(dx * dx + dy * dy));
}

// ---------------- finalize --------------------------------------------------
__global__ __launch_bounds__(256) void k_final(const float* __restrict__ cons,
                                               const float* __restrict__ gen,
                                               float* __restrict__ out) {
    double bal = 0.0, se = 0.0;
    for (int i = threadIdx.x; i < NN; i += 256) {
        float ni  = g_colsum[i] - g_rowsum[i];
        float imb = (cons[i] - gen[i]) - ni;
        bal += (double)imb * (double)imb;
        se  += (double)g_rowsum[i];
    }
#pragma unroll
    for (int o = 16; o > 0; o >>= 1) {
        bal += __shfl_xor_sync(0xffffffffu, bal, o);
        se  += __shfl_xor_sync(0xffffffffu, se, o);
    }
    __shared__ double sb[8], ss[8];
    if ((threadIdx.x & 31) == 0) { sb[threadIdx.x >> 5] = bal; ss[threadIdx.x >> 5] = se; }
    __syncthreads();
    if (threadIdx.x == 0) {
        double B = 0.0, S = 0.0;
#pragma unroll
        for (int w = 0; w < 8; w++) { B += sb[w]; S += ss[w]; }
        float balance = (float)(B / (double)NN);

        float tot = 0.f;
        for (int k = 0; k < KK; k++) {
            float cnt = g_cnt[k];
            if (cnt >= 2.0f) tot += g_ds[k] / (cnt + 1e-6f);
        }
        float numc = (float)g_maxid + 1.0f;
        float spatial = tot / (numc + 1e-6f);

        double clustering = (S - 2.0 * g_within) / ((double)NN * (double)NN + 1e-6);

        float total = 1.0f * balance + 0.5f * spatial + 0.3f * (float)clustering;
        out[0] = total;
        out[1] = balance;
        out[2] = spatial;
        out[3] = (float)clustering;
    }
}

// ---------------- entry -----------------------------------------------------
extern "C" void kernel_launch(void* const* d_in, const int* in_sizes, int n_in,
                              void* d_out, int out_size) {
    const float* E    = (const float*)d_in[0];   // [N,N]
    const float* A    = (const float*)d_in[1];   // [N,64]
    const float* pos  = (const float*)d_in[2];   // [N,2]
    const float* cons = (const float*)d_in[3];   // [N]
    const float* gen  = (const float*)d_in[4];   // [N]
    float* out = (float*)d_out;

    k_zero<<<32, 256>>>();
    k_within<<<dim3(64, 8), 256>>>(E, A);
    k_rowcol<<<256, 256>>>(E);
    k_spatial1<<<32, 256>>>(A, pos);
    k_spatial2<<<32, 256>>>(pos);
    k_final<<<1, 256>>>(cons, gen, out);
}

// round 3
// speedup vs baseline: 1.0046x; 1.0046x over previous
#include <cuda_runtime.h>
#include <math.h>

#define NN 8192
#define KK 64

// ---------------- device scratch (no allocations allowed) ----------------
__device__ double g_within;
__device__ float  g_rowsum[NN];
__device__ float  g_colsum[NN];
__device__ int    g_ids[NN];
__device__ float  g_cnt[KK], g_sx[KK], g_sy[KK], g_ds[KK];
__device__ int    g_maxid;

// ---------------- zero accumulators (graph replays must reset) -----------
__global__ void k_zero() {
    int i = blockIdx.x * blockDim.x + threadIdx.x;
    if (i == 0) { g_within = 0.0; g_maxid = 0; }
    if (i < KK) { g_cnt[i] = 0.f; g_sx[i] = 0.f; g_sy[i] = 0.f; g_ds[i] = 0.f; }
    if (i < NN) { g_rowsum[i] = 0.f; g_colsum[i] = 0.f; }
}

// ---------------- within = sum_ik A_ik * (E@A)_ik -------------------------
// grid (64, 8): blockIdx.x -> 128-row tile of i, blockIdx.y -> 1024-wide j chunk
// block 256 threads (16x16), each computes an 8(i) x 4(k) fp32 micro-tile.
__global__ __launch_bounds__(256) void k_within(const float* __restrict__ E,
                                                const float* __restrict__ A) {
    __shared__ float Es[128][33];   // +1 pad -> conflict-free read & write
    __shared__ float As[32][64];

    const int i0 = blockIdx.x * 128;
    const int j0 = blockIdx.y * 1024;
    const int tx = threadIdx.x & 15;
    const int ty = threadIdx.x >> 4;

    float acc[8][4];
#pragma unroll
    for (int r = 0; r < 8; r++)
#pragma unroll
        for (int c = 0; c < 4; c++) acc[r][c] = 0.f;

    for (int jc = 0; jc < 1024; jc += 32) {
        const int jb = j0 + jc;
        // load E tile 128x32 (coalesced: 32 consecutive j per warp row)
        {
            const int c  = threadIdx.x & 31;
            const int r0 = threadIdx.x >> 5;
#pragma unroll
            for (int p = 0; p < 16; p++) {
                int r = r0 + p * 8;
                Es[r][c] = E[(size_t)(i0 + r) * NN + (jb + c)];
            }
        }
        // load A tile 32x64
#pragma unroll
        for (int p = 0; p < 8; p++) {
            int idx = threadIdx.x + p * 256;
            int r = idx >> 6, c = idx & 63;
            As[r][c] = A[(size_t)(jb + r) * KK + c];
        }
        __syncthreads();

#pragma unroll 8
        for (int jj = 0; jj < 32; jj++) {
            float4 av = *(const float4*)&As[jj][tx * 4];
            float e[8];
#pragma unroll
            for (int r = 0; r < 8; r++) e[r] = Es[ty * 8 + r][jj];
#pragma unroll
            for (int r = 0; r < 8; r++) {
                acc[r][0] = fmaf(e[r], av.x, acc[r][0]);
                acc[r][1] = fmaf(e[r], av.y, acc[r][1]);
                acc[r][2] = fmaf(e[r], av.z, acc[r][2]);
                acc[r][3] = fmaf(e[r], av.w, acc[r][3]);
            }
        }
        __syncthreads();
    }

    // epilogue: partial within = sum acc[r][c] * A[i, k]
    float part = 0.f;
#pragma unroll
    for (int r = 0; r < 8; r++) {
        float4 av = *(const float4*)&A[(size_t)(i0 + ty * 8 + r) * KK + tx * 4];
        part = fmaf(acc[r][0], av.x, part);
        part = fmaf(acc[r][1], av.y, part);
        part = fmaf(acc[r][2], av.z, part);
        part = fmaf(acc[r][3], av.w, part);
    }
#pragma unroll
    for (int o = 16; o > 0; o >>= 1) part += __shfl_xor_sync(0xffffffffu, part, o);

    __shared__ double warpsum[8];
    if ((threadIdx.x & 31) == 0) warpsum[threadIdx.x >> 5] = (double)part;
    __syncthreads();
    if (threadIdx.x == 0) {
        double s = 0.0;
#pragma unroll
        for (int w = 0; w < 8; w++) s += warpsum[w];
        atomicAdd(&g_within, s);
    }
}

// ---------------- rowsum / colsum of E ------------------------------------
// 256 blocks x 256 threads; block b owns rows [32b, 32b+32).
__global__ __launch_bounds__(256) void k_rowcol(const float* __restrict__ E) {
    const int rowbase = blockIdx.x * 32;
    const int t = threadIdx.x;
    float4 csum[8];
#pragma unroll
    for (int p = 0; p < 8; p++) csum[p] = make_float4(0.f, 0.f, 0.f, 0.f);

    for (int r = 0; r < 32; r++) {
        const float4* Erow = (const float4*)(E + (size_t)(rowbase + r) * NN);
        float rs = 0.f;
#pragma unroll
        for (int p = 0; p < 8; p++) {
            float4 v = Erow[t + p * 256];
            csum[p].x += v.x; csum[p].y += v.y; csum[p].z += v.z; csum[p].w += v.w;
            rs += (v.x + v.y) + (v.z + v.w);
        }
#pragma unroll
        for (int o = 16; o > 0; o >>= 1) rs += __shfl_xor_sync(0xffffffffu, rs, o);
        if ((t & 31) == 0) atomicAdd(&g_rowsum[rowbase + r], rs);
    }
#pragma unroll
    for (int p = 0; p < 8; p++) {
        int c = (t + p * 256) * 4;
        atomicAdd(&g_colsum[c + 0], csum[p].x);
        atomicAdd(&g_colsum[c + 1], csum[p].y);
        atomicAdd(&g_colsum[c + 2], csum[p].z);
        atomicAdd(&g_colsum[c + 3], csum[p].w);
    }
}

// ---------------- spatial loss: argmax + segment sums ---------------------
__global__ void k_spatial1(const float* __restrict__ A, const float* __restrict__ pos) {
    int i = blockIdx.x * blockDim.x + threadIdx.x;
    if (i >= NN) return;
    const float4* a4 = (const float4*)(A + (size_t)i * KK);
    float best = -3.402823466e+38f;
    int bi = 0;
#pragma unroll
    for (int q = 0; q < 16; q++) {
        float4 v = a4[q];
        if (v.x > best) { best = v.x; bi = q * 4 + 0; }
        if (v.y > best) { best = v.y; bi = q * 4 + 1; }
        if (v.z > best) { best = v.z; bi = q * 4 + 2; }
        if (v.w > best) { best = v.w; bi = q * 4 + 3; }
    }
    g_ids[i] = bi;
    atomicAdd(&g_cnt[bi], 1.0f);
    atomicAdd(&g_sx[bi], pos[2 * i]);
    atomicAdd(&g_sy[bi], pos[2 * i + 1]);
    atomicMax(&g_maxid, bi);
}

__global__ void k_spatial2(const float* __restrict__ pos) {
    int i = blockIdx.x * blockDim.x + threadIdx.x;
    if (i >= NN) return;
    int c = g_ids[i];
    float cnt = g_cnt[c] + 1e-6f;
    float cx = g_sx[c] / cnt, cy = g_sy[c] / cnt;
    float dx = pos[2 * i] - cx, dy = pos[2 * i + 1] - cy;
    atomicAdd(&g_ds[c], sqrtf(dx * dx + dy * dy));
}

// ---------------- finalize --------------------------------------------------
__global__ __launch_bounds__(256) void k_final(const float* __restrict__ cons,
                                               const float* __restrict__ gen,
                                               float* __restrict__ out) {
    double bal = 0.0, se = 0.0;
    for (int i = threadIdx.x; i < NN; i += 256) {
        float ni  = g_colsum[i] - g_rowsum[i];
        float imb = (cons[i] - gen[i]) - ni;
        bal += (double)imb * (double)imb;
        se  += (double)g_rowsum[i];
    }
#pragma unroll
    for (int o = 16; o > 0; o >>= 1) {
        bal += __shfl_xor_sync(0xffffffffu, bal, o);
        se  += __shfl_xor_sync(0xffffffffu, se, o);
    }
    __shared__ double sb[8], ss[8];
    if ((threadIdx.x & 31) == 0) { sb[threadIdx.x >> 5] = bal; ss[threadIdx.x >> 5] = se; }
    __syncthreads();
    if (threadIdx.x == 0) {
        double B = 0.0, S = 0.0;
#pragma unroll
        for (int w = 0; w < 8; w++) { B += sb[w]; S += ss[w]; }
        float balance = (float)(B / (double)NN);

        float tot = 0.f;
        for (int k = 0; k < KK; k++) {
            float cnt = g_cnt[k];
            if (cnt >= 2.0f) tot += g_ds[k] / (cnt + 1e-6f);
        }
        float numc = (float)g_maxid + 1.0f;
        float spatial = tot / (numc + 1e-6f);

        double clustering = (S - 2.0 * g_within) / ((double)NN * (double)NN + 1e-6);

        float total = 1.0f * balance + 0.5f * spatial + 0.3f * (float)clustering;
        out[0] = total;
        out[1] = balance;
        out[2] = spatial;
        out[3] = (float)clustering;
    }
}

// ---------------- entry -----------------------------------------------------
extern "C" void kernel_launch(void* const* d_in, const int* in_sizes, int n_in,
                              void* d_out, int out_size) {
    const float* E    = (const float*)d_in[0];   // [N,N]
    const float* A    = (const float*)d_in[1];   // [N,64]
    const float* pos  = (const float*)d_in[2];   // [N,2]
    const float* cons = (const float*)d_in[3];   // [N]
    const float* gen  = (const float*)d_in[4];   // [N]
    float* out = (float*)d_out;

    k_zero<<<32, 256>>>();
    k_within<<<dim3(64, 8), 256>>>(E, A);
    k_rowcol<<<256, 256>>>(E);
    k_spatial1<<<32, 256>>>(A, pos);
    k_spatial2<<<32, 256>>>(pos);
    k_final<<<1, 256>>>(cons, gen, out);
}

// round 5
// speedup vs baseline: 3.0352x; 3.0212x over previous
#include <cuda_runtime.h>
#include <cuda_fp16.h>
#include <cstdint>
#include <string.h>
#include <math.h>

#define NN 8192
#define KC 64
#define JRANGE 4096
#define JSTEP 64
#define NSTAGE (JRANGE/JSTEP)

__device__ double g_within;
__device__ float  g_rowsum[NN];
__device__ float  g_colsum[NN];
__device__ int    g_ids[NN];
__device__ float  g_cnt[KC], g_sx[KC], g_sy[KC], g_ds[KC];
__device__ int    g_maxid;
__device__ __half g_AT[KC * NN];   // A^T in fp16, [64][8192]

__device__ __forceinline__ uint32_t smem_u32(const void* p) {
    uint32_t a;
    asm("{ .reg .u64 t; cvta.to.shared.u64 t, %1; cvt.u32.u64 %0, t; }" : "=r"(a) : "l"(p));
    return a;
}
#define LDSM4(r0, r1, r2, r3, a) \
    asm volatile("ldmatrix.sync.aligned.m8n8.x4.shared.b16 {%0,%1,%2,%3}, [%4];" \
        : "=r"(r0), "=r"(r1), "=r"(r2), "=r"(r3) : "r"(a))
#define MMA16816(c, a0, a1, a2, a3, b0, b1) \
    asm volatile("mma.sync.aligned.m16n8k16.row.col.f32.f16.f16.f32 " \
        "{%0,%1,%2,%3}, {%4,%5,%6,%7}, {%8,%9}, {%0,%1,%2,%3};" \
        : "+f"((c)[0]), "+f"((c)[1]), "+f"((c)[2]), "+f"((c)[3]) \
        : "r"(a0), "r"(a1), "r"(a2), "r"(a3), "r"(b0), "r"(b1))

__device__ __forceinline__ uint32_t h2u(__half2 v) { uint32_t u; memcpy(&u, &v, 4); return u; }

// smem layout
#define OFF_COL 0
#define OFF_TMP 16384
#define OFF_BUF 20480
#define BUFSZ   40960     // Eh 16K | El 16K | B 8K
#define OFF_B   32768
#define SMEM_MAIN (OFF_BUF + 2*BUFSZ)   // 102400

__global__ void k_zero() {
    int i = blockIdx.x * blockDim.x + threadIdx.x;
    if (i == 0) { g_within = 0.0; g_maxid = 0; }
    if (i < KC) { g_cnt[i] = 0.f; g_sx[i] = 0.f; g_sy[i] = 0.f; g_ds[i] = 0.f; }
    if (i < NN) { g_rowsum[i] = 0.f; g_colsum[i] = 0.f; }
}

__global__ __launch_bounds__(256) void k_prepA(const float* __restrict__ A) {
    int j = blockIdx.x * 256 + threadIdx.x;
#pragma unroll 4
    for (int k = 0; k < KC; k += 4) {
        float4 v = *(const float4*)(A + (size_t)j * KC + k);
        g_AT[(k + 0) * NN + j] = __float2half_rn(v.x);
        g_AT[(k + 1) * NN + j] = __float2half_rn(v.y);
        g_AT[(k + 2) * NN + j] = __float2half_rn(v.z);
        g_AT[(k + 3) * NN + j] = __float2half_rn(v.w);
    }
}

__global__ __launch_bounds__(256, 1)
void k_main(const float* __restrict__ E, const float* __restrict__ A) {
    extern __shared__ char smem[];
    const uint32_t sb = smem_u32(smem);
    const int tid = threadIdx.x, warp = tid >> 5, lane = tid & 31;
    const int strip = blockIdx.x >> 1, jh = blockIdx.x & 1;
    const size_t i0 = (size_t)strip * 128;
    const int j0 = jh * JRANGE;

    float* colsm = (float*)(smem + OFF_COL);
    float* tmp   = (float*)(smem + OFF_TMP);
    for (int i = tid; i < JRANGE; i += 256) colsm[i] = 0.f;
    __syncthreads();

    const int c4 = tid & 15, rb = tid >> 4;
    float rows_acc[8];
    float acc[8][4];
#pragma unroll
    for (int p = 0; p < 8; p++) rows_acc[p] = 0.f;
#pragma unroll
    for (int t = 0; t < 8; t++)
#pragma unroll
        for (int q = 0; q < 4; q++) acc[t][q] = 0.f;

    const float* Ebase = E + i0 * NN + j0;
    float4 ev[8]; uint4 bv[2];
#pragma unroll
    for (int p = 0; p < 8; p++)
        ev[p] = *(const float4*)(Ebase + (size_t)(rb + 16 * p) * NN + c4 * 4);
#pragma unroll
    for (int q = 0; q < 2; q++) {
        int g = tid + q * 256, rn = g >> 3, c16 = g & 7;
        bv[q] = *(const uint4*)(g_AT + rn * NN + j0 + c16 * 8);
    }

    for (int s = 0; s < NSTAGE; s++) {
        const int b = s & 1;
        char* buf = smem + OFF_BUF + b * BUFSZ;
        const uint32_t bufu = sb + OFF_BUF + b * BUFSZ;

        // ---- row/col partial sums from registers ----
        float cs0 = 0.f, cs1 = 0.f, cs2 = 0.f, cs3 = 0.f;
#pragma unroll
        for (int p = 0; p < 8; p++) {
            cs0 += ev[p].x; cs1 += ev[p].y; cs2 += ev[p].z; cs3 += ev[p].w;
            rows_acc[p] += (ev[p].x + ev[p].y) + (ev[p].z + ev[p].w);
        }
        cs0 += __shfl_xor_sync(~0u, cs0, 16);
        cs1 += __shfl_xor_sync(~0u, cs1, 16);
        cs2 += __shfl_xor_sync(~0u, cs2, 16);
        cs3 += __shfl_xor_sync(~0u, cs3, 16);
        if (lane < 16) {
            float* tw = tmp + (s & 1) * 512 + warp * 64 + c4 * 4;
            tw[0] = cs0; tw[1] = cs1; tw[2] = cs2; tw[3] = cs3;
        }

        // ---- fp32 -> fp16 hi/lo ----
        uint2 hi8[8], lo8[8];
#pragma unroll
        for (int p = 0; p < 8; p++) {
            float4 v = ev[p];
            __half2 h01 = __floats2half2_rn(v.x, v.y);
            __half2 h23 = __floats2half2_rn(v.z, v.w);
            __half2 l01 = __floats2half2_rn(v.x - __low2float(h01), v.y - __high2float(h01));
            __half2 l23 = __floats2half2_rn(v.z - __low2float(h23), v.w - __high2float(h23));
            hi8[p] = make_uint2(h2u(h01), h2u(h23));
            lo8[p] = make_uint2(h2u(l01), h2u(l23));
        }

        // ---- STS (SW128 swizzle: xor bits[6:4] with row bits) ----
#pragma unroll
        for (int p = 0; p < 8; p++) {
            int r = rb + 16 * p;
            uint32_t off = (uint32_t)(r * 128 + c4 * 8);
            off ^= (uint32_t)((r & 7) << 4);
            *(uint2*)(buf + off)         = hi8[p];
            *(uint2*)(buf + 16384 + off) = lo8[p];
        }
#pragma unroll
        for (int q = 0; q < 2; q++) {
            int g = tid + q * 256, rn = g >> 3, c16 = g & 7;
            uint32_t off = (uint32_t)(rn * 128 + c16 * 16);
            off ^= (uint32_t)((rn & 7) << 4);
            *(uint4*)(buf + OFF_B + off) = bv[q];
        }

        // ---- prefetch next stage ----
        if (s + 1 < NSTAGE) {
            const int jc = (s + 1) * JSTEP;
#pragma unroll
            for (int p = 0; p < 8; p++)
                ev[p] = *(const float4*)(Ebase + (size_t)(rb + 16 * p) * NN + jc + c4 * 4);
#pragma unroll
            for (int q = 0; q < 2; q++) {
                int g = tid + q * 256, rn = g >> 3, c16 = g & 7;
                bv[q] = *(const uint4*)(g_AT + rn * NN + j0 + jc + c16 * 8);
            }
        }
        __syncthreads();

        // ---- colsum finalize ----
        if (tid < 64) {
            const float* tr = tmp + (s & 1) * 512 + tid;
            float a = 0.f;
#pragma unroll
            for (int w = 0; w < 8; w++) a += tr[w * 64];
            colsm[s * JSTEP + tid] += a;
        }

        // ---- ldmatrix + mma ----
        const uint32_t ehb = bufu, elb = bufu + 16384, bbb = bufu + OFF_B;
        const int arow = lane & 15;
        const uint32_t abyte = (uint32_t)((lane >> 4) << 4);
#pragma unroll
        for (int ks = 0; ks < 4; ks++) {
            uint32_t aoff = (uint32_t)((16 * warp + arow) * 128 + ks * 32) + abyte;
            aoff ^= (uint32_t)((arow & 7) << 4);
            uint32_t ah0, ah1, ah2, ah3, al0, al1, al2, al3;
            LDSM4(ah0, ah1, ah2, ah3, ehb + aoff);
            LDSM4(al0, al1, al2, al3, elb + aoff);
#pragma unroll
            for (int np = 0; np < 4; np++) {
                uint32_t brow = (uint32_t)(16 * np + arow);
                uint32_t boff = brow * 128 + (uint32_t)(ks * 32) + abyte;
                boff ^= ((brow & 7) << 4);
                uint32_t b0, b1, b2, b3;
                LDSM4(b0, b1, b2, b3, bbb + boff);
                MMA16816(acc[2 * np],     ah0, ah1, ah2, ah3, b0, b2);
                MMA16816(acc[2 * np],     al0, al1, al2, al3, b0, b2);
                MMA16816(acc[2 * np + 1], ah0, ah1, ah2, ah3, b1, b3);
                MMA16816(acc[2 * np + 1], al0, al1, al2, al3, b1, b3);
            }
        }
    }

    // ---- rowsum reduce over the 16 j-group threads ----
#pragma unroll
    for (int p = 0; p < 8; p++) {
        float v = rows_acc[p];
        v += __shfl_xor_sync(~0u, v, 1);
        v += __shfl_xor_sync(~0u, v, 2);
        v += __shfl_xor_sync(~0u, v, 4);
        v += __shfl_xor_sync(~0u, v, 8);
        if (c4 == 0) atomicAdd(&g_rowsum[i0 + rb + 16 * p], v);
    }
    for (int i = tid; i < JRANGE; i += 256) atomicAdd(&g_colsum[j0 + i], colsm[i]);

    // ---- within epilogue: dot accumulators with A rows ----
    // fragment: c0=C[r][2c], c1=C[r][2c+1], c2=C[r+8][2c], c3=C[r+8][2c+1]
    {
        const size_t ru = i0 + 16 * warp + (lane >> 2);
        const int col = 2 * (lane & 3);
        float part = 0.f;
#pragma unroll
        for (int t = 0; t < 8; t++) {
            float2 au = *(const float2*)(A + ru * KC + 8 * t + col);
            float2 ad = *(const float2*)(A + (ru + 8) * KC + 8 * t + col);
            part += acc[t][0] * au.x + acc[t][1] * au.y
                  + acc[t][2] * ad.x + acc[t][3] * ad.y;
        }
#pragma unroll
        for (int o = 16; o > 0; o >>= 1) part += __shfl_xor_sync(~0u, part, o);
        if (lane == 0) atomicAdd(&g_within, (double)part);
    }
}

__global__ __launch_bounds__(256) void k_spatial1(const float* __restrict__ A,
                                                  const float* __restrict__ pos) {
    __shared__ float scnt[KC], ssx[KC], ssy[KC];
    __shared__ int smax;
    int t = threadIdx.x;
    if (t < KC) { scnt[t] = 0.f; ssx[t] = 0.f; ssy[t] = 0.f; }
    if (t == 0) smax = 0;
    __syncthreads();
    int i = blockIdx.x * 256 + t;
    const float4* a4 = (const float4*)(A + (size_t)i * KC);
    float best = -3.402823466e+38f; int bi = 0;
#pragma unroll
    for (int q = 0; q < 16; q++) {
        float4 v = a4[q];
        if (v.x > best) { best = v.x; bi = q * 4; }
        if (v.y > best) { best = v.y; bi = q * 4 + 1; }
        if (v.z > best) { best = v.z; bi = q * 4 + 2; }
        if (v.w > best) { best = v.w; bi = q * 4 + 3; }
    }
    g_ids[i] = bi;
    atomicAdd(&scnt[bi], 1.0f);
    atomicAdd(&ssx[bi], pos[2 * i]);
    atomicAdd(&ssy[bi], pos[2 * i + 1]);
    atomicMax(&smax, bi);
    __syncthreads();
    if (t < KC && scnt[t] != 0.f) {
        atomicAdd(&g_cnt[t], scnt[t]);
        atomicAdd(&g_sx[t], ssx[t]);
        atomicAdd(&g_sy[t], ssy[t]);
    }
    if (t == 0) atomicMax(&g_maxid, smax);
}

__global__ __launch_bounds__(256) void k_spatial2(const float* __restrict__ pos) {
    __shared__ float sds[KC];
    int t = threadIdx.x;
    if (t < KC) sds[t] = 0.f;
    __syncthreads();
    int i = blockIdx.x * 256 + t;
    int c = g_ids[i];
    float cnt = g_cnt[c] + 1e-6f;
    float dx = pos[2 * i] - g_sx[c] / cnt;
    float dy = pos[2 * i + 1] - g_sy[c] / cnt;
    atomicAdd(&sds[c], sqrtf(dx * dx + dy * dy));
    __syncthreads();
    if (t < KC && sds[t] != 0.f) atomicAdd(&g_ds[t], sds[t]);
}

__global__ __launch_bounds__(256) void k_final(const float* __restrict__ cons,
                                               const float* __restrict__ gen,
                                               float* __restrict__ out) {
    double bal = 0.0, se = 0.0;
    for (int i = threadIdx.x; i < NN; i += 256) {
        float ni = g_colsum[i] - g_rowsum[i];
        float imb = (cons[i] - gen[i]) - ni;
        bal += (double)imb * (double)imb;
        se  += (double)g_rowsum[i];
    }
#pragma unroll
    for (int o = 16; o > 0; o >>= 1) {
        bal += __shfl_xor_sync(~0u, bal, o);
        se  += __shfl_xor_sync(~0u, se, o);
    }
    __shared__ double sbv[8], ssv[8];
    if ((threadIdx.x & 31) == 0) { sbv[threadIdx.x >> 5] = bal; ssv[threadIdx.x >> 5] = se; }
    __syncthreads();
    if (threadIdx.x == 0) {
        double B = 0.0, S = 0.0;
#pragma unroll
        for (int w = 0; w < 8; w++) { B += sbv[w]; S += ssv[w]; }
        float balance = (float)(B / (double)NN);
        float tot = 0.f;
        for (int k = 0; k < KC; k++)
            if (g_cnt[k] >= 2.0f) tot += g_ds[k] / (g_cnt[k] + 1e-6f);
        float spatial = tot / ((float)g_maxid + 1.0f + 1e-6f);
        double clustering = (S - 2.0 * g_within) / ((double)NN * (double)NN + 1e-6);
        out[0] = 1.0f * balance + 0.5f * spatial + 0.3f * (float)clustering;
        out[1] = balance;
        out[2] = spatial;
        out[3] = (float)clustering;
    }
}

extern "C" void kernel_launch(void* const* d_in, const int* in_sizes, int n_in,
                              void* d_out, int out_size) {
    const float* E    = (const float*)d_in[0];
    const float* A    = (const float*)d_in[1];
    const float* pos  = (const float*)d_in[2];
    const float* cons = (const float*)d_in[3];
    const float* gen  = (const float*)d_in[4];
    float* out = (float*)d_out;

    cudaFuncSetAttribute(k_main, cudaFuncAttributeMaxDynamicSharedMemorySize, SMEM_MAIN);
    k_zero<<<32, 256>>>();
    k_prepA<<<32, 256>>>(A);
    k_main<<<128, 256, SMEM_MAIN>>>(E, A);
    k_spatial1<<<32, 256>>>(A, pos);
    k_spatial2<<<32, 256>>>(pos);
    k_final<<<1, 256>>>(cons, gen, out);
}

// round 6
// speedup vs baseline: 4.0469x; 1.3333x over previous
#include <cuda_runtime.h>
#include <cuda_fp16.h>
#include <cstdint>
#include <string.h>
#include <math.h>

#define NN 8192
#define KC 64
#define JRANGE 2048
#define JSTEP 64
#define NSTAGE (JRANGE/JSTEP)

__device__ double g_within;
__device__ float  g_rowsum[NN];
__device__ float  g_colsum[NN];
__device__ int    g_ids[NN];
__device__ float  g_cnt[KC], g_sx[KC], g_sy[KC], g_ds[KC];
__device__ int    g_maxid;
__device__ __half g_AT[KC * NN];   // A^T fp16 [64][8192]

__device__ __forceinline__ uint32_t smem_u32(const void* p) {
    uint32_t a;
    asm("{ .reg .u64 t; cvta.to.shared.u64 t, %1; cvt.u32.u64 %0, t; }" : "=r"(a) : "l"(p));
    return a;
}
#define LDSM4(r0, r1, r2, r3, a) \
    asm volatile("ldmatrix.sync.aligned.m8n8.x4.shared.b16 {%0,%1,%2,%3}, [%4];" \
        : "=r"(r0), "=r"(r1), "=r"(r2), "=r"(r3) : "r"(a))
#define MMA16816(c, a0, a1, a2, a3, b0, b1) \
    asm volatile("mma.sync.aligned.m16n8k16.row.col.f32.f16.f16.f32 " \
        "{%0,%1,%2,%3}, {%4,%5,%6,%7}, {%8,%9}, {%0,%1,%2,%3};" \
        : "+f"((c)[0]), "+f"((c)[1]), "+f"((c)[2]), "+f"((c)[3]) \
        : "r"(a0), "r"(a1), "r"(a2), "r"(a3), "r"(b0), "r"(b1))

__device__ __forceinline__ uint32_t h2u(__half2 v) { uint32_t u; memcpy(&u, &v, 4); return u; }

// smem layout
#define OFF_COL 0               // 2048 floats = 8KB
#define OFF_TMP 8192            // 2*512 floats = 4KB
#define OFF_BUF 12288
#define BUFSZ   24576           // E fp16 16KB | B fp16 8KB
#define OFF_B   16384
#define SMEM_MAIN (OFF_BUF + 2*BUFSZ)   // 61440

__global__ void k_zero() {
    int i = blockIdx.x * blockDim.x + threadIdx.x;
    if (i == 0) { g_within = 0.0; g_maxid = 0; }
    if (i < KC) { g_cnt[i] = 0.f; g_sx[i] = 0.f; g_sy[i] = 0.f; g_ds[i] = 0.f; }
    if (i < NN) { g_rowsum[i] = 0.f; g_colsum[i] = 0.f; }
}

__global__ __launch_bounds__(256) void k_prepA(const float* __restrict__ A) {
    int j = blockIdx.x * 256 + threadIdx.x;
#pragma unroll 4
    for (int k = 0; k < KC; k += 4) {
        float4 v = *(const float4*)(A + (size_t)j * KC + k);
        g_AT[(k + 0) * NN + j] = __float2half_rn(v.x);
        g_AT[(k + 1) * NN + j] = __float2half_rn(v.y);
        g_AT[(k + 2) * NN + j] = __float2half_rn(v.z);
        g_AT[(k + 3) * NN + j] = __float2half_rn(v.w);
    }
}

__global__ __launch_bounds__(256, 2)
void k_main(const float* __restrict__ E, const float* __restrict__ A) {
    extern __shared__ char smem[];
    const uint32_t sb = smem_u32(smem);
    const int tid = threadIdx.x, warp = tid >> 5, lane = tid & 31;
    const int strip = blockIdx.x >> 2, jq = blockIdx.x & 3;
    const size_t i0 = (size_t)strip * 128;
    const int j0 = jq * JRANGE;

    float* colsm = (float*)(smem + OFF_COL);
    float* tmp   = (float*)(smem + OFF_TMP);
    for (int i = tid; i < JRANGE; i += 256) colsm[i] = 0.f;
    __syncthreads();

    const int c4 = tid & 15, rb = tid >> 4;
    float rows_acc[8];
    float acc[8][4];   // t = (a<<2)|(np<<1)|h
#pragma unroll
    for (int p = 0; p < 8; p++) rows_acc[p] = 0.f;
#pragma unroll
    for (int t = 0; t < 8; t++)
#pragma unroll
        for (int q = 0; q < 4; q++) acc[t][q] = 0.f;

    const float* Ebase = E + i0 * NN + j0;
    float4 ev[8]; uint4 bv[2];
#pragma unroll
    for (int p = 0; p < 8; p++)
        ev[p] = *(const float4*)(Ebase + (size_t)(rb + 16 * p) * NN + c4 * 4);
#pragma unroll
    for (int q = 0; q < 2; q++) {
        int g = tid + q * 256, rn = g >> 3, c16 = g & 7;
        bv[q] = *(const uint4*)(g_AT + rn * NN + j0 + c16 * 8);
    }

    const int mw = warp & 3, nw = warp >> 2;

    for (int s = 0; s < NSTAGE; s++) {
        const int b = s & 1;
        char* buf = smem + OFF_BUF + b * BUFSZ;
        const uint32_t bufu = sb + OFF_BUF + b * BUFSZ;

        // row/col partial sums from registers
        float cs0 = 0.f, cs1 = 0.f, cs2 = 0.f, cs3 = 0.f;
#pragma unroll
        for (int p = 0; p < 8; p++) {
            cs0 += ev[p].x; cs1 += ev[p].y; cs2 += ev[p].z; cs3 += ev[p].w;
            rows_acc[p] += (ev[p].x + ev[p].y) + (ev[p].z + ev[p].w);
        }
        cs0 += __shfl_xor_sync(~0u, cs0, 16);
        cs1 += __shfl_xor_sync(~0u, cs1, 16);
        cs2 += __shfl_xor_sync(~0u, cs2, 16);
        cs3 += __shfl_xor_sync(~0u, cs3, 16);
        if (lane < 16) {
            float* tw = tmp + (s & 1) * 512 + warp * 64 + c4 * 4;
            tw[0] = cs0; tw[1] = cs1; tw[2] = cs2; tw[3] = cs3;
        }

        // fp32 -> fp16 (single precision level)
        uint2 hi8[8];
#pragma unroll
        for (int p = 0; p < 8; p++) {
            hi8[p] = make_uint2(h2u(__floats2half2_rn(ev[p].x, ev[p].y)),
                                h2u(__floats2half2_rn(ev[p].z, ev[p].w)));
        }
        // STS with SW128-style swizzle
#pragma unroll
        for (int p = 0; p < 8; p++) {
            int r = rb + 16 * p;
            uint32_t off = (uint32_t)(r * 128 + c4 * 8);
            off ^= (uint32_t)((r & 7) << 4);
            *(uint2*)(buf + off) = hi8[p];
        }
#pragma unroll
        for (int q = 0; q < 2; q++) {
            int g = tid + q * 256, rn = g >> 3, c16 = g & 7;
            uint32_t off = (uint32_t)(rn * 128 + c16 * 16);
            off ^= (uint32_t)((rn & 7) << 4);
            *(uint4*)(buf + OFF_B + off) = bv[q];
        }

        // prefetch next stage
        if (s + 1 < NSTAGE) {
            const int jc = (s + 1) * JSTEP;
#pragma unroll
            for (int p = 0; p < 8; p++)
                ev[p] = *(const float4*)(Ebase + (size_t)(rb + 16 * p) * NN + jc + c4 * 4);
#pragma unroll
            for (int q = 0; q < 2; q++) {
                int g = tid + q * 256, rn = g >> 3, c16 = g & 7;
                bv[q] = *(const uint4*)(g_AT + rn * NN + j0 + jc + c16 * 8);
            }
        }
        __syncthreads();

        // colsum finalize
        if (tid < 64) {
            const float* tr = tmp + (s & 1) * 512 + tid;
            float a = 0.f;
#pragma unroll
            for (int w = 0; w < 8; w++) a += tr[w * 64];
            colsm[s * JSTEP + tid] += a;
        }

        // ldmatrix + mma: warp tile M32(mw) x N32(nw)
        const int arow = lane & 15;
        const uint32_t abyte = (uint32_t)((lane >> 4) << 4);
#pragma unroll
        for (int ks = 0; ks < 4; ks++) {
            uint32_t a0r, a1r, a2r, a3r, a4r, a5r, a6r, a7r;
            {
                uint32_t r0 = (uint32_t)(32 * mw + arow);
                uint32_t off0 = (r0 * 128 + (uint32_t)(ks * 32) + abyte) ^ ((r0 & 7) << 4);
                LDSM4(a0r, a1r, a2r, a3r, bufu + off0);
                uint32_t r1 = r0 + 16;
                uint32_t off1 = (r1 * 128 + (uint32_t)(ks * 32) + abyte) ^ ((r1 & 7) << 4);
                LDSM4(a4r, a5r, a6r, a7r, bufu + off1);
            }
            uint32_t b0, b1, b2, b3, b4, b5, b6, b7;
            {
                uint32_t n0 = (uint32_t)(32 * nw + arow);
                uint32_t off0 = (n0 * 128 + (uint32_t)(ks * 32) + abyte) ^ ((n0 & 7) << 4);
                LDSM4(b0, b1, b2, b3, bufu + OFF_B + off0);
                uint32_t n1 = n0 + 16;
                uint32_t off1 = (n1 * 128 + (uint32_t)(ks * 32) + abyte) ^ ((n1 & 7) << 4);
                LDSM4(b4, b5, b6, b7, bufu + OFF_B + off1);
            }
            MMA16816(acc[0], a0r, a1r, a2r, a3r, b0, b2);
            MMA16816(acc[1], a0r, a1r, a2r, a3r, b1, b3);
            MMA16816(acc[2], a0r, a1r, a2r, a3r, b4, b6);
            MMA16816(acc[3], a0r, a1r, a2r, a3r, b5, b7);
            MMA16816(acc[4], a4r, a5r, a6r, a7r, b0, b2);
            MMA16816(acc[5], a4r, a5r, a6r, a7r, b1, b3);
            MMA16816(acc[6], a4r, a5r, a6r, a7r, b4, b6);
            MMA16816(acc[7], a4r, a5r, a6r, a7r, b5, b7);
        }
    }

    // rowsum reduce across 16 j-group threads
#pragma unroll
    for (int p = 0; p < 8; p++) {
        float v = rows_acc[p];
        v += __shfl_xor_sync(~0u, v, 1);
        v += __shfl_xor_sync(~0u, v, 2);
        v += __shfl_xor_sync(~0u, v, 4);
        v += __shfl_xor_sync(~0u, v, 8);
        if (c4 == 0) atomicAdd(&g_rowsum[i0 + rb + 16 * p], v);
    }
    for (int i = tid; i < JRANGE; i += 256) atomicAdd(&g_colsum[j0 + i], colsm[i]);

    // within epilogue: acc[(a<<2)|(np<<1)|h] -> rows i0+32mw+16a+(lane>>2)(+8), cols 32nw+16np+8h+2(lane&3)
    {
        float part = 0.f;
        const int crow = lane >> 2, ccol = 2 * (lane & 3);
#pragma unroll
        for (int a = 0; a < 2; a++)
#pragma unroll
            for (int np = 0; np < 2; np++)
#pragma unroll
                for (int h = 0; h < 2; h++) {
                    const float* cp = acc[(a << 2) | (np << 1) | h];
                    size_t ru = i0 + 32 * mw + 16 * a + crow;
                    int col = 32 * nw + 16 * np + 8 * h + ccol;
                    float2 au = *(const float2*)(A + ru * KC + col);
                    float2 ad = *(const float2*)(A + (ru + 8) * KC + col);
                    part += cp[0] * au.x + cp[1] * au.y + cp[2] * ad.x + cp[3] * ad.y;
                }
#pragma unroll
        for (int o = 16; o > 0; o >>= 1) part += __shfl_xor_sync(~0u, part, o);
        __syncthreads();
        if (lane == 0) tmp[warp] = part;
        __syncthreads();
        if (tid == 0) {
            float s = 0.f;
#pragma unroll
            for (int w = 0; w < 8; w++) s += tmp[w];
            atomicAdd(&g_within, (double)s);
        }
    }
}

__global__ __launch_bounds__(256) void k_spatial1(const float* __restrict__ A,
                                                  const float* __restrict__ pos) {
    __shared__ float scnt[KC], ssx[KC], ssy[KC];
    __shared__ int smax;
    int t = threadIdx.x;
    if (t < KC) { scnt[t] = 0.f; ssx[t] = 0.f; ssy[t] = 0.f; }
    if (t == 0) smax = 0;
    __syncthreads();
    int i = blockIdx.x * 256 + t;
    const float4* a4 = (const float4*)(A + (size_t)i * KC);
    float best = -3.402823466e+38f; int bi = 0;
#pragma unroll
    for (int q = 0; q < 16; q++) {
        float4 v = a4[q];
        if (v.x > best) { best = v.x; bi = q * 4; }
        if (v.y > best) { best = v.y; bi = q * 4 + 1; }
        if (v.z > best) { best = v.z; bi = q * 4 + 2; }
        if (v.w > best) { best = v.w; bi = q * 4 + 3; }
    }
    g_ids[i] = bi;
    atomicAdd(&scnt[bi], 1.0f);
    atomicAdd(&ssx[bi], pos[2 * i]);
    atomicAdd(&ssy[bi], pos[2 * i + 1]);
    atomicMax(&smax, bi);
    __syncthreads();
    if (t < KC && scnt[t] != 0.f) {
        atomicAdd(&g_cnt[t], scnt[t]);
        atomicAdd(&g_sx[t], ssx[t]);
        atomicAdd(&g_sy[t], ssy[t]);
    }
    if (t == 0) atomicMax(&g_maxid, smax);
}

__global__ __launch_bounds__(256) void k_spatial2(const float* __restrict__ pos) {
    __shared__ float sds[KC];
    int t = threadIdx.x;
    if (t < KC) sds[t] = 0.f;
    __syncthreads();
    int i = blockIdx.x * 256 + t;
    int c = g_ids[i];
    float cnt = g_cnt[c] + 1e-6f;
    float dx = pos[2 * i] - g_sx[c] / cnt;
    float dy = pos[2 * i + 1] - g_sy[c] / cnt;
    atomicAdd(&sds[c], sqrtf(dx * dx + dy * dy));
    __syncthreads();
    if (t < KC && sds[t] != 0.f) atomicAdd(&g_ds[t], sds[t]);
}

__global__ __launch_bounds__(256) void k_final(const float* __restrict__ cons,
                                               const float* __restrict__ gen,
                                               float* __restrict__ out) {
    double bal = 0.0, se = 0.0;
    for (int i = threadIdx.x; i < NN; i += 256) {
        float ni = g_colsum[i] - g_rowsum[i];
        float imb = (cons[i] - gen[i]) - ni;
        bal += (double)imb * (double)imb;
        se  += (double)g_rowsum[i];
    }
#pragma unroll
    for (int o = 16; o > 0; o >>= 1) {
        bal += __shfl_xor_sync(~0u, bal, o);
        se  += __shfl_xor_sync(~0u, se, o);
    }
    __shared__ double sbv[8], ssv[8];
    if ((threadIdx.x & 31) == 0) { sbv[threadIdx.x >> 5] = bal; ssv[threadIdx.x >> 5] = se; }
    __syncthreads();
    if (threadIdx.x == 0) {
        double B = 0.0, S = 0.0;
#pragma unroll
        for (int w = 0; w < 8; w++) { B += sbv[w]; S += ssv[w]; }
        float balance = (float)(B / (double)NN);
        float tot = 0.f;
        for (int k = 0; k < KC; k++)
            if (g_cnt[k] >= 2.0f) tot += g_ds[k] / (g_cnt[k] + 1e-6f);
        float spatial = tot / ((float)g_maxid + 1.0f + 1e-6f);
        double clustering = (S - 2.0 * g_within) / ((double)NN * (double)NN + 1e-6);
        out[0] = 1.0f * balance + 0.5f * spatial + 0.3f * (float)clustering;
        out[1] = balance;
        out[2] = spatial;
        out[3] = (float)clustering;
    }
}

extern "C" void kernel_launch(void* const* d_in, const int* in_sizes, int n_in,
                              void* d_out, int out_size) {
    const float* E    = (const float*)d_in[0];
    const float* A    = (const float*)d_in[1];
    const float* pos  = (const float*)d_in[2];
    const float* cons = (const float*)d_in[3];
    const float* gen  = (const float*)d_in[4];
    float* out = (float*)d_out;

    cudaFuncSetAttribute(k_main, cudaFuncAttributeMaxDynamicSharedMemorySize, SMEM_MAIN);
    // k_main placed at launch index 3 so ncu's skip-window captures it
    k_zero<<<32, 256>>>();
    k_prepA<<<32, 256>>>(A);
    k_spatial1<<<32, 256>>>(A, pos);
    k_main<<<256, 256, SMEM_MAIN>>>(E, A);
    k_spatial2<<<32, 256>>>(pos);
    k_final<<<1, 256>>>(cons, gen, out);
}